// round 7
// baseline (speedup 1.0000x reference)
#include <cuda_runtime.h>
#include <math.h>
#include <stdint.h>

#define BB 8
#define NN 4096
#define FF 64
#define OO 64
#define KK 20
#define NPTS (BB*NN)
#define FULLM 0xFFFFFFFFu
#define JCH 128
#define NCHUNK (NN/JCH)

// ---------------- scratch (device globals: no allocation allowed) ----------------
__device__ float  g_xT[NPTS*FF];   // transposed: [b][f][n]
__device__ float  g_sq[NPTS];
__device__ float  g_u[NPTS*OO];
__device__ float  g_v[NPTS*OO];
__device__ int    g_idx[NPTS*KK];
__device__ float  g_hmax[NPTS*OO];
__device__ float  g_hmin[NPTS*OO];
__device__ double g_sum[OO];
__device__ double g_ssq[OO];
__device__ float  g_scale[OO];
__device__ float  g_shift[OO];
__device__ int    g_ctr;

// packed dual-fp32 FMA (Blackwell f32x2 pipe, PTX-only)
__device__ __forceinline__ void ffma2(unsigned long long &acc,
                                      unsigned long long a,
                                      unsigned long long b) {
    asm("fma.rn.f32x2 %0, %1, %2, %0;" : "+l"(acc) : "l"(a), "l"(b));
}
__device__ __forceinline__ unsigned long long dup2(float v) {
    unsigned long long r;
    asm("mov.b64 %0, {%1, %1};" : "=l"(r) : "f"(v));
    return r;
}
__device__ __forceinline__ void unpack2(unsigned long long p, float &lo, float &hi) {
    asm("mov.b64 {%0, %1}, %2;" : "=f"(lo), "=f"(hi) : "l"(p));
}
__device__ __forceinline__ void cp16(void* dst_smem, const void* src_g) {
    unsigned s = (unsigned)__cvta_generic_to_shared(dst_smem);
    asm volatile("cp.async.cg.shared.global [%0], [%1], 16;" :: "r"(s), "l"(src_g) : "memory");
}
__device__ __forceinline__ void cp_commit() {
    asm volatile("cp.async.commit_group;" ::: "memory");
}
__device__ __forceinline__ void cp_wait0() {
    asm volatile("cp.async.wait_group 0;" ::: "memory");
}

// ---------------- transpose x[b][n][f] -> xT[b][f][n] ----------------
__global__ __launch_bounds__(256) void k_tr(const float* __restrict__ x) {
    __shared__ float t[32][33];
    const int b = blockIdx.z, n0 = blockIdx.x * 32, f0 = blockIdx.y * 32;
    const int tx = threadIdx.x, ty = threadIdx.y;
    const float* xb = x + (size_t)b * NN * FF;
    #pragma unroll
    for (int r = 0; r < 4; ++r)
        t[ty + 8*r][tx] = xb[(n0 + ty + 8*r)*FF + f0 + tx];
    __syncthreads();
    float* xT = g_xT + (size_t)b * FF * NN;
    #pragma unroll
    for (int r = 0; r < 4; ++r)
        xT[(f0 + ty + 8*r)*NN + n0 + tx] = t[tx][ty + 8*r];
}

// ---------------- u = x*(W1-W2)^T, v = x*W2^T, norms; block0 zeroes stats --------
__global__ __launch_bounds__(256) void k_uv(const float* __restrict__ x,
                                            const float* __restrict__ W) {
    if (blockIdx.x == 0) {
        if (threadIdx.x < OO) { g_sum[threadIdx.x] = 0.0; g_ssq[threadIdx.x] = 0.0; }
        if (threadIdx.x == 0) g_ctr = 0;
    }

    __shared__ float Wm[FF*OO];   // (W1 - W2)[f][o]
    __shared__ float W2s[FF*OO];  // W2[f][o]
    __shared__ float xbuf[8][FF];

    for (int i = threadIdx.x; i < FF*OO; i += 256) {
        int f = i >> 6, o = i & 63;
        float w1 = W[o*128 + f];
        float w2 = W[o*128 + 64 + f];
        Wm[f*OO + o]  = w1 - w2;
        W2s[f*OO + o] = w2;
    }
    __syncthreads();

    const int lane = threadIdx.x & 31, warp = threadIdx.x >> 5;
    const int p0 = blockIdx.x * 64 + warp * 8;

    for (int pp = 0; pp < 8; ++pp) {
        const int p = p0 + pp;
        const float* xr = x + (size_t)p * FF;
        float x0 = xr[lane], x1 = xr[lane + 32];
        xbuf[warp][lane] = x0; xbuf[warp][lane + 32] = x1;
        __syncwarp();

        float s = x0*x0 + x1*x1;
        #pragma unroll
        for (int o = 16; o; o >>= 1) s += __shfl_xor_sync(FULLM, s, o);
        if (lane == 0) g_sq[p] = s;

        float u0 = 0.f, u1 = 0.f, v0 = 0.f, v1 = 0.f;
        #pragma unroll
        for (int f = 0; f < FF; ++f) {
            float xv = xbuf[warp][f];
            u0 = fmaf(Wm[f*OO + lane],       xv, u0);
            u1 = fmaf(Wm[f*OO + lane + 32],  xv, u1);
            v0 = fmaf(W2s[f*OO + lane],      xv, v0);
            v1 = fmaf(W2s[f*OO + lane + 32], xv, v1);
        }
        g_u[(size_t)p*OO + lane]      = u0;
        g_u[(size_t)p*OO + lane + 32] = u1;
        g_v[(size_t)p*OO + lane]      = v0;
        g_v[(size_t)p*OO + lane + 32] = v1;
        __syncwarp();
    }
}

// ---------------- KNN: 64 i x 128 j tiles, f32x2 FMA, cp.async pipeline ----------
// Dynamic smem: xsi (16KB) + xsj[2] (2 x 32KB) = 80KB. One barrier per chunk.
// Staging reads xT (f-major) so every 16B smem chunk maps to 16B contiguous gmem.
__global__ __launch_bounds__(256, 2) void k_knn() {
    extern __shared__ __align__(16) float smem[];
    float* xsi = smem;              // [f][i], swizzle chunk4 = i4 ^ (f&15)
    float* xsj = smem + FF*64;      // two buffers of [f][j], chunk4 = j4 ^ (f&31)

    const int b  = blockIdx.y;
    const int i0 = blockIdx.x * 64;
    const float* xT  = g_xT + (size_t)b * FF * NN;
    const float* sqb = g_sq + b * NN;
    const int tid = threadIdx.x, lane = tid & 31, warp = tid >> 5;
    const int fs = tid >> 2, rem = tid & 3;   // staging role: row fs, chunk slot rem

    // issue async staging: i-tile + j-chunk 0 (one group)
    const float* srow = xT + fs * NN;
    #pragma unroll
    for (int k = 0; k < 4; ++k) {
        int i4 = rem + 4*k;
        cp16(&xsi[fs*64 + 4*(i4 ^ (fs & 15))], srow + i0 + 4*i4);
    }
    #pragma unroll
    for (int k = 0; k < 8; ++k) {
        int j4 = rem + 4*k;
        cp16(&xsj[fs*128 + 4*(j4 ^ (fs & 31))], srow + 4*j4);
    }
    cp_commit();

    float sqi[8];
    #pragma unroll
    for (int r = 0; r < 8; ++r) sqi[r] = sqb[i0 + 8*warp + r];

    // sorted top-20: lanes 0..19 hold ascending (val, idx); curmax = slot-19 value
    float bestv[8], curmax[8];
    int   besti[8];
    #pragma unroll
    for (int r = 0; r < 8; ++r) { bestv[r] = INFINITY; curmax[r] = INFINITY; besti[r] = 0; }

    for (int jc = 0; jc < NCHUNK; ++jc) {
        const int j0 = jc * JCH;
        const float* cur = xsj + (jc & 1) * (FF*128);

        cp_wait0();          // this chunk's data has landed (issued a full chunk ago)
        __syncthreads();     // ... in every warp

        // issue NEXT chunk (fire-and-forget; covered by this chunk's compute)
        if (jc + 1 < NCHUNK) {
            float* nxt = xsj + ((jc + 1) & 1) * (FF*128);
            const int jn0 = j0 + JCH;
            #pragma unroll
            for (int k = 0; k < 8; ++k) {
                int j4 = rem + 4*k;
                cp16(&nxt[fs*128 + 4*(j4 ^ (fs & 31))], srow + jn0 + 4*j4);
            }
            cp_commit();
        }

        unsigned long long accP[4][4];
        #pragma unroll
        for (int m = 0; m < 4; ++m)
            #pragma unroll
            for (int q = 0; q < 4; ++q) accP[m][q] = 0ull;

        #pragma unroll 16
        for (int f = 0; f < FF; ++f) {
            ulonglong2 aA = *(const ulonglong2*)&xsi[f*64 + 4*((2*warp)     ^ (f & 15))];
            ulonglong2 aB = *(const ulonglong2*)&xsi[f*64 + 4*((2*warp + 1) ^ (f & 15))];
            float4 bv = *(const float4*)&cur[f*128 + 4*(lane ^ (f & 31))];
            unsigned long long b0 = dup2(bv.x), b1 = dup2(bv.y),
                               b2 = dup2(bv.z), b3 = dup2(bv.w);
            ffma2(accP[0][0], aA.x, b0); ffma2(accP[0][1], aA.x, b1);
            ffma2(accP[0][2], aA.x, b2); ffma2(accP[0][3], aA.x, b3);
            ffma2(accP[1][0], aA.y, b0); ffma2(accP[1][1], aA.y, b1);
            ffma2(accP[1][2], aA.y, b2); ffma2(accP[1][3], aA.y, b3);
            ffma2(accP[2][0], aB.x, b0); ffma2(accP[2][1], aB.x, b1);
            ffma2(accP[2][2], aB.x, b2); ffma2(accP[2][3], aB.x, b3);
            ffma2(accP[3][0], aB.y, b0); ffma2(accP[3][1], aB.y, b1);
            ffma2(accP[3][2], aB.y, b2); ffma2(accP[3][3], aB.y, b3);
        }

        float4 sq4 = *(const float4*)&sqb[j0 + 4*lane];
        const float sqj[4] = {sq4.x, sq4.y, sq4.z, sq4.w};

        #pragma unroll
        for (int m = 0; m < 4; ++m) {
            float dot[2][4];
            #pragma unroll
            for (int q = 0; q < 4; ++q) unpack2(accP[m][q], dot[0][q], dot[1][q]);

            #pragma unroll
            for (int h = 0; h < 2; ++h) {
                const int r  = 2*m + h;
                const int ig = i0 + 8*warp + r;
                const bool diag = (ig >> 7) == (j0 >> 7);
                float d[4];
                #pragma unroll
                for (int q = 0; q < 4; ++q)
                    d[q] = fmaf(-2.f, dot[h][q], sqi[r] + sqj[q]);
                if (diag) {
                    #pragma unroll
                    for (int q = 0; q < 4; ++q)
                        if (ig == j0 + 4*lane + q) d[q] = INFINITY;
                }
                float dmin = fminf(fminf(d[0], d[1]), fminf(d[2], d[3]));
                if (__ballot_sync(FULLM, dmin < curmax[r])) {
                    #pragma unroll
                    for (int q = 0; q < 4; ++q) {
                        float v = d[q];
                        unsigned mmask = __ballot_sync(FULLM, v < curmax[r]);
                        while (mmask) {
                            int src  = __ffs(mmask) - 1;
                            float cv = __shfl_sync(FULLM, v, src);
                            int   cj = j0 + 4*src + q;
                            float upv = __shfl_up_sync(FULLM, bestv[r], 1);
                            int   upi = __shfl_up_sync(FULLM, besti[r], 1);
                            float p18 = __shfl_sync(FULLM, bestv[r], 18);
                            bool shift = (lane < KK) && (bestv[r] > cv);
                            unsigned pm = __ballot_sync(FULLM, shift);
                            int first = __ffs(pm) - 1;
                            if (shift) {
                                bestv[r] = (lane == first) ? cv : upv;
                                besti[r] = (lane == first) ? cj : upi;
                            }
                            curmax[r] = fmaxf(p18, cv);
                            if (lane == src) v = INFINITY;
                            mmask = __ballot_sync(FULLM, v < curmax[r]);
                        }
                    }
                }
            }
        }
    }

    #pragma unroll
    for (int r = 0; r < 8; ++r)
        if (lane < KK)
            g_idx[(size_t)(b*NN + i0 + 8*warp + r)*KK + lane] = besti[r];
}

// ---------------- fuse: h = u_n + v_j, max/min, channel sums; last block -> BN ---
__global__ __launch_bounds__(256) void k_fuse(const float* __restrict__ gamma,
                                              const float* __restrict__ beta) {
    const int tid = threadIdx.x, lane = tid & 31, warp = tid >> 5;
    const int p0 = blockIdx.x * 64 + warp * 8;
    float s0 = 0.f, s1 = 0.f, q0 = 0.f, q1 = 0.f;

    for (int pp = 0; pp < 8; ++pp) {
        const int p = p0 + pp;
        const int vbase = (p >> 12) << 18;   // (p/4096)*4096*64
        int myj = 0;
        if (lane < KK) myj = g_idx[(size_t)p*KK + lane];
        float u0 = g_u[(size_t)p*OO + lane];
        float u1 = g_u[(size_t)p*OO + lane + 32];
        float mx0 = -INFINITY, mx1 = -INFINITY, mn0 = INFINITY, mn1 = INFINITY;
        #pragma unroll
        for (int k = 0; k < KK; ++k) {
            int j = __shfl_sync(FULLM, myj, k);
            const float* vp = g_v + vbase + j*OO;
            float v0 = vp[lane], v1 = vp[lane + 32];
            float h0 = u0 + v0, h1 = u1 + v1;
            mx0 = fmaxf(mx0, h0); mn0 = fminf(mn0, h0);
            mx1 = fmaxf(mx1, h1); mn1 = fminf(mn1, h1);
            s0 += h0; q0 = fmaf(h0, h0, q0);
            s1 += h1; q1 = fmaf(h1, h1, q1);
        }
        g_hmax[(size_t)p*OO + lane]      = mx0;
        g_hmax[(size_t)p*OO + lane + 32] = mx1;
        g_hmin[(size_t)p*OO + lane]      = mn0;
        g_hmin[(size_t)p*OO + lane + 32] = mn1;
    }

    __shared__ float sb[8][OO], qb[8][OO];
    sb[warp][lane] = s0; sb[warp][lane + 32] = s1;
    qb[warp][lane] = q0; qb[warp][lane + 32] = q1;
    __syncthreads();
    if (tid < OO) {
        float a = 0.f, c = 0.f;
        #pragma unroll
        for (int w = 0; w < 8; ++w) { a += sb[w][tid]; c += qb[w][tid]; }
        atomicAdd(&g_sum[tid], (double)a);
        atomicAdd(&g_ssq[tid], (double)c);
    }
    __syncthreads();

    __shared__ int amLast;
    if (tid == 0) {
        __threadfence();
        amLast = (atomicAdd(&g_ctr, 1) == (int)gridDim.x - 1);
    }
    __syncthreads();
    if (amLast) {
        __threadfence();
        if (tid < OO) {
            const double cnt = (double)NPTS * (double)KK;
            double m   = g_sum[tid] / cnt;
            double var = g_ssq[tid] / cnt - m * m;
            float a = gamma[tid] * rsqrtf((float)var + 1e-5f);
            g_scale[tid] = a;
            g_shift[tid] = beta[tid] - (float)m * a;
        }
    }
}

// ---------------- apply BN + ReLU to the pooled extrema ----------------
__global__ __launch_bounds__(256) void k_final(float* __restrict__ out) {
    int t = blockIdx.x * 256 + threadIdx.x;          // 4 floats per thread
    float4 mx = ((const float4*)g_hmax)[t];
    float4 mn = ((const float4*)g_hmin)[t];
    int o = (t * 4) & 63;
    float a0 = g_scale[o+0], a1 = g_scale[o+1], a2 = g_scale[o+2], a3 = g_scale[o+3];
    float4 r;
    r.x = fmaxf(fmaf(a0, (a0 >= 0.f) ? mx.x : mn.x, g_shift[o+0]), 0.f);
    r.y = fmaxf(fmaf(a1, (a1 >= 0.f) ? mx.y : mn.y, g_shift[o+1]), 0.f);
    r.z = fmaxf(fmaf(a2, (a2 >= 0.f) ? mx.z : mn.z, g_shift[o+2]), 0.f);
    r.w = fmaxf(fmaf(a3, (a3 >= 0.f) ? mx.w : mn.w, g_shift[o+3]), 0.f);
    ((float4*)out)[t] = r;
}

extern "C" void kernel_launch(void* const* d_in, const int* in_sizes, int n_in,
                              void* d_out, int out_size) {
    const float* x     = (const float*)d_in[0];
    const float* W     = (const float*)d_in[1];
    // d_in[2] (conv bias b) cancels exactly under BatchNorm: unused.
    const float* gamma = (const float*)d_in[3];
    const float* beta  = (const float*)d_in[4];
    float* out = (float*)d_out;

    const int knn_smem = (FF*64 + 2*FF*128) * sizeof(float);   // 80 KB
    cudaFuncSetAttribute(k_knn, cudaFuncAttributeMaxDynamicSharedMemorySize, knn_smem);

    k_tr   <<<dim3(NN/32, FF/32, BB), dim3(32, 8)>>>(x);
    k_uv   <<<NPTS/64, 256>>>(x, W);
    k_knn  <<<dim3(NN/64, BB), 256, knn_smem>>>();
    k_fuse <<<NPTS/64, 256>>>(gamma, beta);
    k_final<<<NPTS*OO/1024, 256>>>(out);
}

// round 10
// speedup vs baseline: 1.2649x; 1.2649x over previous
#include <cuda_runtime.h>
#include <cuda_fp16.h>
#include <math.h>
#include <stdint.h>

#define BB 8
#define NN 4096
#define FF 64
#define OO 64
#define KK 20
#define NPTS (BB*NN)
#define FULLM 0xFFFFFFFFu
#define JCH 128
#define NCHUNK (NN/JCH)
#define ITILE 64
#define DSTRIDE 132

// ---------------- scratch (device globals: no allocation allowed) ----------------
__device__ __half  g_xhi[NPTS*FF];
__device__ __half  g_xlo[NPTS*FF];
__device__ float  g_sq[NPTS];
__device__ float  g_u[NPTS*OO];
__device__ float  g_v[NPTS*OO];
__device__ int    g_idx[NPTS*KK];
__device__ float  g_hmax[NPTS*OO];
__device__ float  g_hmin[NPTS*OO];
__device__ double g_sum[OO];
__device__ double g_ssq[OO];
__device__ float  g_scale[OO];
__device__ float  g_shift[OO];
__device__ int    g_ctr;

// ---------------- smem layout for k_knn (byte offsets into dynamic smem) ---------
#define SM_AHI   0                    // 64 x 64 half = 8192
#define SM_ALO   8192
#define SM_BHI   16384                // 128 x 64 half = 16384
#define SM_BLO   32768
#define SM_DST   49152                // 64 x 132 float = 33792
#define SM_SQJ   82944                // 128 float
#define SM_HV    83456                // 20 x 128 float = 10240
#define SM_HI    93696                // 20 x 128 int   = 10240
#define SM_TOTAL 103936

// ---------------- PTX helpers ----------------
__device__ __forceinline__ uint32_t smem_u32(const void* p) {
    uint32_t a;
    asm("{ .reg .u64 t; cvta.to.shared.u64 t, %1; cvt.u32.u64 %0, t; }" : "=r"(a) : "l"(p));
    return a;
}
__device__ __forceinline__ void ldmx4(uint32_t* r, uint32_t addr) {
    asm volatile("ldmatrix.sync.aligned.m8n8.x4.shared.b16 {%0,%1,%2,%3}, [%4];"
                 : "=r"(r[0]), "=r"(r[1]), "=r"(r[2]), "=r"(r[3]) : "r"(addr));
}
__device__ __forceinline__ void ldmx2(uint32_t* r, uint32_t addr) {
    asm volatile("ldmatrix.sync.aligned.m8n8.x2.shared.b16 {%0,%1}, [%2];"
                 : "=r"(r[0]), "=r"(r[1]) : "r"(addr));
}
__device__ __forceinline__ void mma16816(float* c, const uint32_t* a, const uint32_t* b) {
    asm volatile(
        "mma.sync.aligned.m16n8k16.row.col.f32.f16.f16.f32 "
        "{%0,%1,%2,%3}, {%4,%5,%6,%7}, {%8,%9}, {%0,%1,%2,%3};"
        : "+f"(c[0]), "+f"(c[1]), "+f"(c[2]), "+f"(c[3])
        : "r"(a[0]), "r"(a[1]), "r"(a[2]), "r"(a[3]), "r"(b[0]), "r"(b[1]));
}

// ---------------- split x into f16 hi/lo ----------------
__global__ __launch_bounds__(256) void k_split(const float* __restrict__ x) {
    int i = blockIdx.x * 256 + threadIdx.x;
    float2 v = ((const float2*)x)[i];
    __half h0 = __float2half(v.x);
    __half h1 = __float2half(v.y);
    __half l0 = __float2half(v.x - __half2float(h0));
    __half l1 = __float2half(v.y - __half2float(h1));
    ((__half2*)g_xhi)[i] = __halves2half2(h0, h1);
    ((__half2*)g_xlo)[i] = __halves2half2(l0, l1);
}

// ---------------- u = x*(W1-W2)^T, v = x*W2^T, norms; block0 zeroes stats --------
__global__ __launch_bounds__(256) void k_uv(const float* __restrict__ x,
                                            const float* __restrict__ W) {
    if (blockIdx.x == 0) {
        if (threadIdx.x < OO) { g_sum[threadIdx.x] = 0.0; g_ssq[threadIdx.x] = 0.0; }
        if (threadIdx.x == 0) g_ctr = 0;
    }
    __shared__ float Wm[FF*OO];
    __shared__ float W2s[FF*OO];
    __shared__ float xbuf[8][FF];

    for (int i = threadIdx.x; i < FF*OO; i += 256) {
        int f = i >> 6, o = i & 63;
        float w1 = W[o*128 + f];
        float w2 = W[o*128 + 64 + f];
        Wm[f*OO + o]  = w1 - w2;
        W2s[f*OO + o] = w2;
    }
    __syncthreads();

    const int lane = threadIdx.x & 31, warp = threadIdx.x >> 5;
    const int p0 = blockIdx.x * 64 + warp * 8;

    for (int pp = 0; pp < 8; ++pp) {
        const int p = p0 + pp;
        const float* xr = x + (size_t)p * FF;
        float x0 = xr[lane], x1 = xr[lane + 32];
        xbuf[warp][lane] = x0; xbuf[warp][lane + 32] = x1;
        __syncwarp();

        float s = x0*x0 + x1*x1;
        #pragma unroll
        for (int o = 16; o; o >>= 1) s += __shfl_xor_sync(FULLM, s, o);
        if (lane == 0) g_sq[p] = s;

        float u0 = 0.f, u1 = 0.f, v0 = 0.f, v1 = 0.f;
        #pragma unroll
        for (int f = 0; f < FF; ++f) {
            float xv = xbuf[warp][f];
            u0 = fmaf(Wm[f*OO + lane],       xv, u0);
            u1 = fmaf(Wm[f*OO + lane + 32],  xv, u1);
            v0 = fmaf(W2s[f*OO + lane],      xv, v0);
            v1 = fmaf(W2s[f*OO + lane + 32], xv, v1);
        }
        g_u[(size_t)p*OO + lane]      = u0;
        g_u[(size_t)p*OO + lane + 32] = u1;
        g_v[(size_t)p*OO + lane]      = v0;
        g_v[(size_t)p*OO + lane + 32] = v1;
        __syncwarp();
    }
}

// ---------------- KNN via mma.sync (HMMA): 64i x 128j, f16-split 3-pass ----------
// 128 thr = 4 warps. Warp w owns rows 16w..16w+15. XOR-swizzled tiles for ldmatrix.
// Distances land in smem DST; 2 selector threads per row run 20-slot max-heaps.
__global__ __launch_bounds__(128, 2) void k_knn() {
    extern __shared__ __align__(16) char sm[];
    const int tid = threadIdx.x, lane = tid & 31, wid = tid >> 5;
    const int b = blockIdx.y, i0 = blockIdx.x * ITILE;
    const uint32_t smb = smem_u32(sm);

    float* DST = (float*)(sm + SM_DST);
    float* SQJ = (float*)(sm + SM_SQJ);
    float* HV  = (float*)(sm + SM_HV);
    int*   HIx = (int*)(sm + SM_HI);

    // ---- stage A tiles (hi/lo), swizzled: chunk' = chunk ^ (row&7) ----
    {
        const float4* ghi = (const float4*)(g_xhi + (size_t)(b*NN + i0) * FF);
        const float4* glo = (const float4*)(g_xlo + (size_t)(b*NN + i0) * FF);
        #pragma unroll
        for (int c = 0; c < 4; ++c) {
            int off16 = tid + 128*c;                  // 512 chunks of 16B
            int row = off16 >> 3, ch = off16 & 7;
            uint32_t so = (uint32_t)(row*128 + ((ch ^ (row & 7)) << 4));
            *(float4*)(sm + SM_AHI + so) = ghi[off16];
            *(float4*)(sm + SM_ALO + so) = glo[off16];
        }
    }

    // ---- heap init ----
    #pragma unroll
    for (int s = 0; s < KK; ++s) { HV[s*128 + tid] = INFINITY; HIx[s*128 + tid] = 0; }
    float rootv = INFINITY;
    const int selrow = tid >> 1, selhalf = tid & 1;
    const int ig = i0 + selrow;

    // sqi for MMA epilogue (per lane: rows r0, r0+8)
    const int er0 = wid*16 + (lane >> 2);
    const float sqi0 = g_sq[b*NN + i0 + er0];
    const float sqi8 = g_sq[b*NN + i0 + er0 + 8];

    __syncthreads();

    // ---- load A fragments once (4 k-steps, hi & lo) ----
    uint32_t Ah[4][4], Al[4][4];
    #pragma unroll
    for (int kk = 0; kk < 4; ++kk) {
        int row = wid*16 + (lane & 15);
        int ch  = kk*2 + (lane >> 4);
        uint32_t off = (uint32_t)(row*128 + ((ch ^ (row & 7)) << 4));
        ldmx4(Ah[kk], smb + SM_AHI + off);
        ldmx4(Al[kk], smb + SM_ALO + off);
    }

    for (int jc = 0; jc < NCHUNK; ++jc) {
        const int j0 = jc * JCH;

        // ---- stage B tiles (hi/lo) + sqj ----
        {
            const float4* ghi = (const float4*)(g_xhi + (size_t)(b*NN + j0) * FF);
            const float4* glo = (const float4*)(g_xlo + (size_t)(b*NN + j0) * FF);
            #pragma unroll
            for (int c = 0; c < 8; ++c) {
                int off16 = tid + 128*c;              // 1024 chunks
                int row = off16 >> 3, ch = off16 & 7;
                uint32_t so = (uint32_t)(row*128 + ((ch ^ (row & 7)) << 4));
                *(float4*)(sm + SM_BHI + so) = ghi[off16];
                *(float4*)(sm + SM_BLO + so) = glo[off16];
            }
            SQJ[tid] = g_sq[b*NN + j0 + tid];
        }
        __syncthreads();

        // ---- MMA over 16 n8-tiles: 3 passes (hihi, hilo, lohi), K=64 ----
        #pragma unroll 4
        for (int t = 0; t < 16; ++t) {
            uint32_t bh[4][2], bl[4][2];
            const int bn = 8*t + (lane & 7);
            const int cb = (lane >> 3) & 1;
            #pragma unroll
            for (int kk = 0; kk < 4; ++kk) {
                uint32_t off = (uint32_t)(bn*128 + (((kk*2 + cb) ^ (bn & 7)) << 4));
                ldmx2(bh[kk], smb + SM_BHI + off);
                ldmx2(bl[kk], smb + SM_BLO + off);
            }
            float acc[4] = {0.f, 0.f, 0.f, 0.f};
            #pragma unroll
            for (int kk = 0; kk < 4; ++kk) mma16816(acc, Ah[kk], bh[kk]);
            #pragma unroll
            for (int kk = 0; kk < 4; ++kk) mma16816(acc, Ah[kk], bl[kk]);
            #pragma unroll
            for (int kk = 0; kk < 4; ++kk) mma16816(acc, Al[kk], bh[kk]);

            // epilogue: dist = sqi + sqj - 2 dot -> DST
            const int c0 = 8*t + 2*(lane & 3);
            float2 sj = *(const float2*)&SQJ[c0];
            float2 d0, d1;
            d0.x = fmaf(-2.f, acc[0], sqi0 + sj.x);
            d0.y = fmaf(-2.f, acc[1], sqi0 + sj.y);
            d1.x = fmaf(-2.f, acc[2], sqi8 + sj.x);
            d1.y = fmaf(-2.f, acc[3], sqi8 + sj.y);
            *(float2*)&DST[er0*DSTRIDE + c0]       = d0;
            *(float2*)&DST[(er0 + 8)*DSTRIDE + c0] = d1;
        }
        __syncthreads();

        // ---- selection: 2 threads/row, 64 cols each, smem max-heap ----
        {
            const float* drow = DST + selrow*DSTRIDE + selhalf*64;
            const int jbase = j0 + selhalf*64;
            #pragma unroll 4
            for (int q = 0; q < 16; ++q) {
                float4 dv4 = *(const float4*)&drow[q*4];
                #pragma unroll
                for (int e = 0; e < 4; ++e) {
                    float dv = (&dv4.x)[e];
                    const int jg = jbase + q*4 + e;
                    if (dv < rootv && jg != ig) {
                        int s = 0;
                        for (;;) {
                            int c1 = 2*s + 1;
                            if (c1 >= KK) break;
                            int c2 = c1 + 1;
                            float v1 = HV[c1*128 + tid];
                            float v2 = (c2 < KK) ? HV[c2*128 + tid] : -INFINITY;
                            int   big = (v2 > v1) ? c2 : c1;
                            float bvv = fmaxf(v1, v2);
                            if (bvv <= dv) break;
                            HV[s*128 + tid]  = bvv;
                            HIx[s*128 + tid] = HIx[big*128 + tid];
                            s = big;
                        }
                        HV[s*128 + tid]  = dv;
                        HIx[s*128 + tid] = jg;
                        rootv = HV[tid];
                    }
                }
            }
        }
        __syncthreads();   // selectors done with DST; stagers may overwrite B
    }

    // ---- merge the two half-row heaps (even tid absorbs odd tid's) ----
    if ((tid & 1) == 0) {
        #pragma unroll
        for (int s = 0; s < KK; ++s) {
            float v = HV[s*128 + tid + 1];
            int  ix = HIx[s*128 + tid + 1];
            if (v < rootv) {
                int t2 = 0;
                for (;;) {
                    int c1 = 2*t2 + 1;
                    if (c1 >= KK) break;
                    int c2 = c1 + 1;
                    float v1 = HV[c1*128 + tid];
                    float v2 = (c2 < KK) ? HV[c2*128 + tid] : -INFINITY;
                    int   big = (v2 > v1) ? c2 : c1;
                    float bvv = fmaxf(v1, v2);
                    if (bvv <= v) break;
                    HV[t2*128 + tid]  = bvv;
                    HIx[t2*128 + tid] = HIx[big*128 + tid];
                    t2 = big;
                }
                HV[t2*128 + tid]  = v;
                HIx[t2*128 + tid] = ix;
                rootv = HV[tid];
            }
        }
        #pragma unroll
        for (int s = 0; s < KK; ++s)
            g_idx[(size_t)(b*NN + ig)*KK + s] = HIx[s*128 + tid];
    }
}

// ---------------- fuse: h = u_n + v_j, max/min, channel sums; last block -> BN ---
__global__ __launch_bounds__(256) void k_fuse(const float* __restrict__ gamma,
                                              const float* __restrict__ beta) {
    const int tid = threadIdx.x, lane = tid & 31, warp = tid >> 5;
    const int p0 = blockIdx.x * 64 + warp * 8;
    float s0 = 0.f, s1 = 0.f, q0 = 0.f, q1 = 0.f;

    for (int pp = 0; pp < 8; ++pp) {
        const int p = p0 + pp;
        const int vbase = (p >> 12) << 18;
        int myj = 0;
        if (lane < KK) myj = g_idx[(size_t)p*KK + lane];
        float u0 = g_u[(size_t)p*OO + lane];
        float u1 = g_u[(size_t)p*OO + lane + 32];
        float mx0 = -INFINITY, mx1 = -INFINITY, mn0 = INFINITY, mn1 = INFINITY;
        #pragma unroll
        for (int k = 0; k < KK; ++k) {
            int j = __shfl_sync(FULLM, myj, k);
            const float* vp = g_v + vbase + j*OO;
            float v0 = vp[lane], v1 = vp[lane + 32];
            float h0 = u0 + v0, h1 = u1 + v1;
            mx0 = fmaxf(mx0, h0); mn0 = fminf(mn0, h0);
            mx1 = fmaxf(mx1, h1); mn1 = fminf(mn1, h1);
            s0 += h0; q0 = fmaf(h0, h0, q0);
            s1 += h1; q1 = fmaf(h1, h1, q1);
        }
        g_hmax[(size_t)p*OO + lane]      = mx0;
        g_hmax[(size_t)p*OO + lane + 32] = mx1;
        g_hmin[(size_t)p*OO + lane]      = mn0;
        g_hmin[(size_t)p*OO + lane + 32] = mn1;
    }

    __shared__ float sb[8][OO], qb[8][OO];
    sb[warp][lane] = s0; sb[warp][lane + 32] = s1;
    qb[warp][lane] = q0; qb[warp][lane + 32] = q1;
    __syncthreads();
    if (tid < OO) {
        float a = 0.f, c = 0.f;
        #pragma unroll
        for (int w = 0; w < 8; ++w) { a += sb[w][tid]; c += qb[w][tid]; }
        atomicAdd(&g_sum[tid], (double)a);
        atomicAdd(&g_ssq[tid], (double)c);
    }
    __syncthreads();

    __shared__ int amLast;
    if (tid == 0) {
        __threadfence();
        amLast = (atomicAdd(&g_ctr, 1) == (int)gridDim.x - 1);
    }
    __syncthreads();
    if (amLast) {
        __threadfence();
        if (tid < OO) {
            const double cnt = (double)NPTS * (double)KK;
            double m   = g_sum[tid] / cnt;
            double var = g_ssq[tid] / cnt - m * m;
            float a = gamma[tid] * rsqrtf((float)var + 1e-5f);
            g_scale[tid] = a;
            g_shift[tid] = beta[tid] - (float)m * a;
        }
    }
}

// ---------------- apply BN + ReLU to the pooled extrema ----------------
__global__ __launch_bounds__(256) void k_final(float* __restrict__ out) {
    int t = blockIdx.x * 256 + threadIdx.x;
    float4 mx = ((const float4*)g_hmax)[t];
    float4 mn = ((const float4*)g_hmin)[t];
    int o = (t * 4) & 63;
    float a0 = g_scale[o+0], a1 = g_scale[o+1], a2 = g_scale[o+2], a3 = g_scale[o+3];
    float4 r;
    r.x = fmaxf(fmaf(a0, (a0 >= 0.f) ? mx.x : mn.x, g_shift[o+0]), 0.f);
    r.y = fmaxf(fmaf(a1, (a1 >= 0.f) ? mx.y : mn.y, g_shift[o+1]), 0.f);
    r.z = fmaxf(fmaf(a2, (a2 >= 0.f) ? mx.z : mn.z, g_shift[o+2]), 0.f);
    r.w = fmaxf(fmaf(a3, (a3 >= 0.f) ? mx.w : mn.w, g_shift[o+3]), 0.f);
    ((float4*)out)[t] = r;
}

extern "C" void kernel_launch(void* const* d_in, const int* in_sizes, int n_in,
                              void* d_out, int out_size) {
    const float* x     = (const float*)d_in[0];
    const float* W     = (const float*)d_in[1];
    // d_in[2] (conv bias b) cancels exactly under BatchNorm: unused.
    const float* gamma = (const float*)d_in[3];
    const float* beta  = (const float*)d_in[4];
    float* out = (float*)d_out;

    cudaFuncSetAttribute(k_knn, cudaFuncAttributeMaxDynamicSharedMemorySize, SM_TOTAL);

    k_split<<<NPTS*FF/512, 256>>>(x);
    k_uv   <<<NPTS/64, 256>>>(x, W);
    k_knn  <<<dim3(NN/ITILE, BB), 128, SM_TOTAL>>>();
    k_fuse <<<NPTS/64, 256>>>(gamma, beta);
    k_final<<<NPTS*OO/1024, 256>>>(out);
}

// round 11
// speedup vs baseline: 1.3795x; 1.0906x over previous
#include <cuda_runtime.h>
#include <cuda_fp16.h>
#include <math.h>
#include <stdint.h>

#define BB 8
#define NN 4096
#define FF 64
#define OO 64
#define KK 20
#define NPTS (BB*NN)
#define FULLM 0xFFFFFFFFu
#define JCH 128
#define NCHUNK (NN/JCH)
#define ITILE 64
#define DSTRIDE 132

// ---------------- scratch (device globals: no allocation allowed) ----------------
__device__ __half  g_xhi[NPTS*FF];
__device__ __half  g_xlo[NPTS*FF];
__device__ float  g_sq[NPTS];
__device__ float  g_u[NPTS*OO];
__device__ float  g_v[NPTS*OO];
__device__ int    g_idx[NPTS*KK];
__device__ float  g_hmax[NPTS*OO];
__device__ float  g_hmin[NPTS*OO];
__device__ double g_sum[OO];
__device__ double g_ssq[OO];
__device__ float  g_scale[OO];
__device__ float  g_shift[OO];
__device__ int    g_ctr;

// ---------------- smem layout for k_knn (byte offsets into dynamic smem) ---------
#define SM_AHI   0                    // 64 x 64 half = 8192
#define SM_ALO   8192
#define SM_BHI   16384                // 128 x 64 half = 16384
#define SM_BLO   32768
#define SM_DST   49152                // 64 x 132 float = 33792
#define SM_SQJ   82944                // 128 float
#define SM_HV    83456                // 20 x 128 float = 10240
#define SM_HI    93696                // 20 x 128 int   = 10240
#define SM_TOTAL 103936

// ---------------- PTX helpers ----------------
__device__ __forceinline__ uint32_t smem_u32(const void* p) {
    uint32_t a;
    asm("{ .reg .u64 t; cvta.to.shared.u64 t, %1; cvt.u32.u64 %0, t; }" : "=r"(a) : "l"(p));
    return a;
}
__device__ __forceinline__ void ldmx4(uint32_t* r, uint32_t addr) {
    asm volatile("ldmatrix.sync.aligned.m8n8.x4.shared.b16 {%0,%1,%2,%3}, [%4];"
                 : "=r"(r[0]), "=r"(r[1]), "=r"(r[2]), "=r"(r[3]) : "r"(addr));
}
__device__ __forceinline__ void mma16816(float* c, const uint32_t* a, const uint32_t* b) {
    asm volatile(
        "mma.sync.aligned.m16n8k16.row.col.f32.f16.f16.f32 "
        "{%0,%1,%2,%3}, {%4,%5,%6,%7}, {%8,%9}, {%0,%1,%2,%3};"
        : "+f"(c[0]), "+f"(c[1]), "+f"(c[2]), "+f"(c[3])
        : "r"(a[0]), "r"(a[1]), "r"(a[2]), "r"(a[3]), "r"(b[0]), "r"(b[1]));
}

// ---------------- split x into f16 hi/lo ----------------
__global__ __launch_bounds__(256) void k_split(const float* __restrict__ x) {
    int i = blockIdx.x * 256 + threadIdx.x;
    float2 v = ((const float2*)x)[i];
    __half h0 = __float2half(v.x);
    __half h1 = __float2half(v.y);
    __half l0 = __float2half(v.x - __half2float(h0));
    __half l1 = __float2half(v.y - __half2float(h1));
    ((__half2*)g_xhi)[i] = __halves2half2(h0, h1);
    ((__half2*)g_xlo)[i] = __halves2half2(l0, l1);
}

// ---------------- u = x*(W1-W2)^T, v = x*W2^T, norms; block0 zeroes stats --------
__global__ __launch_bounds__(256) void k_uv(const float* __restrict__ x,
                                            const float* __restrict__ W) {
    if (blockIdx.x == 0) {
        if (threadIdx.x < OO) { g_sum[threadIdx.x] = 0.0; g_ssq[threadIdx.x] = 0.0; }
        if (threadIdx.x == 0) g_ctr = 0;
    }
    __shared__ float Wm[FF*OO];
    __shared__ float W2s[FF*OO];
    __shared__ float xbuf[8][FF];

    for (int i = threadIdx.x; i < FF*OO; i += 256) {
        int f = i >> 6, o = i & 63;
        float w1 = W[o*128 + f];
        float w2 = W[o*128 + 64 + f];
        Wm[f*OO + o]  = w1 - w2;
        W2s[f*OO + o] = w2;
    }
    __syncthreads();

    const int lane = threadIdx.x & 31, warp = threadIdx.x >> 5;
    const int p0 = blockIdx.x * 64 + warp * 8;

    for (int pp = 0; pp < 8; ++pp) {
        const int p = p0 + pp;
        const float* xr = x + (size_t)p * FF;
        float x0 = xr[lane], x1 = xr[lane + 32];
        xbuf[warp][lane] = x0; xbuf[warp][lane + 32] = x1;
        __syncwarp();

        float s = x0*x0 + x1*x1;
        #pragma unroll
        for (int o = 16; o; o >>= 1) s += __shfl_xor_sync(FULLM, s, o);
        if (lane == 0) g_sq[p] = s;

        float u0 = 0.f, u1 = 0.f, v0 = 0.f, v1 = 0.f;
        #pragma unroll
        for (int f = 0; f < FF; ++f) {
            float xv = xbuf[warp][f];
            u0 = fmaf(Wm[f*OO + lane],       xv, u0);
            u1 = fmaf(Wm[f*OO + lane + 32],  xv, u1);
            v0 = fmaf(W2s[f*OO + lane],      xv, v0);
            v1 = fmaf(W2s[f*OO + lane + 32], xv, v1);
        }
        g_u[(size_t)p*OO + lane]      = u0;
        g_u[(size_t)p*OO + lane + 32] = u1;
        g_v[(size_t)p*OO + lane]      = v0;
        g_v[(size_t)p*OO + lane + 32] = v1;
        __syncwarp();
    }
}

// ---------------- KNN via mma.sync: 64i x 128j, f16-split, 6 indep acc chains ----
// 128 thr = 4 warps. Register-prefetched B staging; 2 barriers per chunk.
__global__ __launch_bounds__(128, 2) void k_knn() {
    extern __shared__ __align__(16) char sm[];
    const int tid = threadIdx.x, lane = tid & 31, wid = tid >> 5;
    const int b = blockIdx.y, i0 = blockIdx.x * ITILE;
    const uint32_t smb = smem_u32(sm);

    float* DST = (float*)(sm + SM_DST);
    float* SQJ = (float*)(sm + SM_SQJ);
    float* HV  = (float*)(sm + SM_HV);
    int*   HIx = (int*)(sm + SM_HI);

    // ---- stage A tiles (hi/lo), swizzled: chunk' = chunk ^ (row&7) ----
    {
        const float4* ghi = (const float4*)(g_xhi + (size_t)(b*NN + i0) * FF);
        const float4* glo = (const float4*)(g_xlo + (size_t)(b*NN + i0) * FF);
        #pragma unroll
        for (int c = 0; c < 4; ++c) {
            int off16 = tid + 128*c;
            int row = off16 >> 3, ch = off16 & 7;
            uint32_t so = (uint32_t)(row*128 + ((ch ^ (row & 7)) << 4));
            *(float4*)(sm + SM_AHI + so) = ghi[off16];
            *(float4*)(sm + SM_ALO + so) = glo[off16];
        }
    }

    // ---- heap init ----
    #pragma unroll
    for (int s = 0; s < KK; ++s) { HV[s*128 + tid] = INFINITY; HIx[s*128 + tid] = 0; }
    float rootv = INFINITY;
    const int selrow = tid >> 1, selhalf = tid & 1;
    const int ig = i0 + selrow;

    const int er0 = wid*16 + (lane >> 2);
    const float sqi0 = g_sq[b*NN + i0 + er0];
    const float sqi8 = g_sq[b*NN + i0 + er0 + 8];

    // ---- prefetch chunk 0 B into registers ----
    float4 pBh[8], pBl[8];
    float sq_pre;
    {
        const float4* ghi = (const float4*)(g_xhi + (size_t)(b*NN) * FF);
        const float4* glo = (const float4*)(g_xlo + (size_t)(b*NN) * FF);
        #pragma unroll
        for (int c = 0; c < 8; ++c) { pBh[c] = ghi[tid + 128*c]; pBl[c] = glo[tid + 128*c]; }
        sq_pre = g_sq[b*NN + tid];
    }

    __syncthreads();

    // ---- load A fragments once (4 k-steps, hi & lo) ----
    uint32_t Ah[4][4], Al[4][4];
    #pragma unroll
    for (int kk = 0; kk < 4; ++kk) {
        int row = wid*16 + (lane & 15);
        int ch  = kk*2 + (lane >> 4);
        uint32_t off = (uint32_t)(row*128 + ((ch ^ (row & 7)) << 4));
        ldmx4(Ah[kk], smb + SM_AHI + off);
        ldmx4(Al[kk], smb + SM_ALO + off);
    }

    for (int jc = 0; jc < NCHUNK; ++jc) {
        const int j0 = jc * JCH;

        // ---- STS prefetched B (registers -> smem, swizzled) ----
        #pragma unroll
        for (int c = 0; c < 8; ++c) {
            int off16 = tid + 128*c;
            int row = off16 >> 3, ch = off16 & 7;
            uint32_t so = (uint32_t)(row*128 + ((ch ^ (row & 7)) << 4));
            *(float4*)(sm + SM_BHI + so) = pBh[c];
            *(float4*)(sm + SM_BLO + so) = pBl[c];
        }
        SQJ[tid] = sq_pre;
        __syncthreads();

        // ---- issue prefetch for next chunk (lands during MMA+selection) ----
        if (jc + 1 < NCHUNK) {
            const int jn = j0 + JCH;
            const float4* ghi = (const float4*)(g_xhi + (size_t)(b*NN + jn) * FF);
            const float4* glo = (const float4*)(g_xlo + (size_t)(b*NN + jn) * FF);
            #pragma unroll
            for (int c = 0; c < 8; ++c) { pBh[c] = ghi[tid + 128*c]; pBl[c] = glo[tid + 128*c]; }
            sq_pre = g_sq[b*NN + jn + tid];
        }

        // ---- MMA over 8 tile-pairs; 6 independent acc chains per pair ----
        // ldmx4 B mapping: m = lane>>3; tile = 2tp + (m>>1); kchunk = kk*2 + (m&1)
        const int bnrow = (lane & 7);
        const int msel  = lane >> 3;
        #pragma unroll
        for (int tp = 0; tp < 8; ++tp) {
            uint32_t bh[4][4], bl[4][4];
            const int bn = 8*(2*tp + (msel >> 1)) + bnrow;
            #pragma unroll
            for (int kk = 0; kk < 4; ++kk) {
                int ch = kk*2 + (msel & 1);
                uint32_t off = (uint32_t)(bn*128 + ((ch ^ (bn & 7)) << 4));
                ldmx4(bh[kk], smb + SM_BHI + off);
                ldmx4(bl[kk], smb + SM_BLO + off);
            }
            float hh0[4] = {0,0,0,0}, hl0[4] = {0,0,0,0}, lh0[4] = {0,0,0,0};
            float hh1[4] = {0,0,0,0}, hl1[4] = {0,0,0,0}, lh1[4] = {0,0,0,0};
            #pragma unroll
            for (int kk = 0; kk < 4; ++kk) {
                mma16816(hh0, Ah[kk], &bh[kk][0]);
                mma16816(hh1, Ah[kk], &bh[kk][2]);
                mma16816(hl0, Ah[kk], &bl[kk][0]);
                mma16816(hl1, Ah[kk], &bl[kk][2]);
                mma16816(lh0, Al[kk], &bh[kk][0]);
                mma16816(lh1, Al[kk], &bh[kk][2]);
            }
            // epilogue: dist = sqi + sqj - 2*(hh+hl+lh) -> DST, both tiles
            #pragma unroll
            for (int tt = 0; tt < 2; ++tt) {
                const float* hh = tt ? hh1 : hh0;
                const float* hl = tt ? hl1 : hl0;
                const float* lh = tt ? lh1 : lh0;
                const int c0 = 8*(2*tp + tt) + 2*(lane & 3);
                float2 sj = *(const float2*)&SQJ[c0];
                float2 d0, d1;
                d0.x = fmaf(-2.f, (hh[0] + hl[0]) + lh[0], sqi0 + sj.x);
                d0.y = fmaf(-2.f, (hh[1] + hl[1]) + lh[1], sqi0 + sj.y);
                d1.x = fmaf(-2.f, (hh[2] + hl[2]) + lh[2], sqi8 + sj.x);
                d1.y = fmaf(-2.f, (hh[3] + hl[3]) + lh[3], sqi8 + sj.y);
                *(float2*)&DST[er0*DSTRIDE + c0]       = d0;
                *(float2*)&DST[(er0 + 8)*DSTRIDE + c0] = d1;
            }
        }
        __syncthreads();

        // ---- selection: 2 threads/row, 64 cols each, smem max-heap ----
        {
            const float* drow = DST + selrow*DSTRIDE + selhalf*64;
            const int jbase = j0 + selhalf*64;
            #pragma unroll 4
            for (int q = 0; q < 16; ++q) {
                float4 dv4 = *(const float4*)&drow[q*4];
                #pragma unroll
                for (int e = 0; e < 4; ++e) {
                    float dv = (&dv4.x)[e];
                    const int jg = jbase + q*4 + e;
                    if (dv < rootv && jg != ig) {
                        int s = 0;
                        for (;;) {
                            int c1 = 2*s + 1;
                            if (c1 >= KK) break;
                            int c2 = c1 + 1;
                            float v1 = HV[c1*128 + tid];
                            float v2 = (c2 < KK) ? HV[c2*128 + tid] : -INFINITY;
                            int   big = (v2 > v1) ? c2 : c1;
                            float bvv = fmaxf(v1, v2);
                            if (bvv <= dv) break;
                            HV[s*128 + tid]  = bvv;
                            HIx[s*128 + tid] = HIx[big*128 + tid];
                            s = big;
                        }
                        HV[s*128 + tid]  = dv;
                        HIx[s*128 + tid] = jg;
                        rootv = HV[tid];
                    }
                }
            }
        }
        // next loop-top barrier (after STS) orders selection reads vs DST rewrite
    }

    __syncthreads();

    // ---- merge the two half-row heaps (even tid absorbs odd tid's) ----
    if ((tid & 1) == 0) {
        #pragma unroll
        for (int s = 0; s < KK; ++s) {
            float v = HV[s*128 + tid + 1];
            int  ix = HIx[s*128 + tid + 1];
            if (v < rootv) {
                int t2 = 0;
                for (;;) {
                    int c1 = 2*t2 + 1;
                    if (c1 >= KK) break;
                    int c2 = c1 + 1;
                    float v1 = HV[c1*128 + tid];
                    float v2 = (c2 < KK) ? HV[c2*128 + tid] : -INFINITY;
                    int   big = (v2 > v1) ? c2 : c1;
                    float bvv = fmaxf(v1, v2);
                    if (bvv <= v) break;
                    HV[t2*128 + tid]  = bvv;
                    HIx[t2*128 + tid] = HIx[big*128 + tid];
                    t2 = big;
                }
                HV[t2*128 + tid]  = v;
                HIx[t2*128 + tid] = ix;
                rootv = HV[tid];
            }
        }
        #pragma unroll
        for (int s = 0; s < KK; ++s)
            g_idx[(size_t)(b*NN + ig)*KK + s] = HIx[s*128 + tid];
    }
}

// ---------------- fuse: h = u_n + v_j, max/min, channel sums; last block -> BN ---
__global__ __launch_bounds__(256) void k_fuse(const float* __restrict__ gamma,
                                              const float* __restrict__ beta) {
    const int tid = threadIdx.x, lane = tid & 31, warp = tid >> 5;
    const int p0 = blockIdx.x * 64 + warp * 8;
    float s0 = 0.f, s1 = 0.f, q0 = 0.f, q1 = 0.f;

    for (int pp = 0; pp < 8; ++pp) {
        const int p = p0 + pp;
        const int vbase = (p >> 12) << 18;
        int myj = 0;
        if (lane < KK) myj = g_idx[(size_t)p*KK + lane];
        float u0 = g_u[(size_t)p*OO + lane];
        float u1 = g_u[(size_t)p*OO + lane + 32];
        float mx0 = -INFINITY, mx1 = -INFINITY, mn0 = INFINITY, mn1 = INFINITY;
        #pragma unroll
        for (int k = 0; k < KK; ++k) {
            int j = __shfl_sync(FULLM, myj, k);
            const float* vp = g_v + vbase + j*OO;
            float v0 = vp[lane], v1 = vp[lane + 32];
            float h0 = u0 + v0, h1 = u1 + v1;
            mx0 = fmaxf(mx0, h0); mn0 = fminf(mn0, h0);
            mx1 = fmaxf(mx1, h1); mn1 = fminf(mn1, h1);
            s0 += h0; q0 = fmaf(h0, h0, q0);
            s1 += h1; q1 = fmaf(h1, h1, q1);
        }
        g_hmax[(size_t)p*OO + lane]      = mx0;
        g_hmax[(size_t)p*OO + lane + 32] = mx1;
        g_hmin[(size_t)p*OO + lane]      = mn0;
        g_hmin[(size_t)p*OO + lane + 32] = mn1;
    }

    __shared__ float sb[8][OO], qb[8][OO];
    sb[warp][lane] = s0; sb[warp][lane + 32] = s1;
    qb[warp][lane] = q0; qb[warp][lane + 32] = q1;
    __syncthreads();
    if (tid < OO) {
        float a = 0.f, c = 0.f;
        #pragma unroll
        for (int w = 0; w < 8; ++w) { a += sb[w][tid]; c += qb[w][tid]; }
        atomicAdd(&g_sum[tid], (double)a);
        atomicAdd(&g_ssq[tid], (double)c);
    }
    __syncthreads();

    __shared__ int amLast;
    if (tid == 0) {
        __threadfence();
        amLast = (atomicAdd(&g_ctr, 1) == (int)gridDim.x - 1);
    }
    __syncthreads();
    if (amLast) {
        __threadfence();
        if (tid < OO) {
            const double cnt = (double)NPTS * (double)KK;
            double m   = g_sum[tid] / cnt;
            double var = g_ssq[tid] / cnt - m * m;
            float a = gamma[tid] * rsqrtf((float)var + 1e-5f);
            g_scale[tid] = a;
            g_shift[tid] = beta[tid] - (float)m * a;
        }
    }
}

// ---------------- apply BN + ReLU to the pooled extrema ----------------
__global__ __launch_bounds__(256) void k_final(float* __restrict__ out) {
    int t = blockIdx.x * 256 + threadIdx.x;
    float4 mx = ((const float4*)g_hmax)[t];
    float4 mn = ((const float4*)g_hmin)[t];
    int o = (t * 4) & 63;
    float a0 = g_scale[o+0], a1 = g_scale[o+1], a2 = g_scale[o+2], a3 = g_scale[o+3];
    float4 r;
    r.x = fmaxf(fmaf(a0, (a0 >= 0.f) ? mx.x : mn.x, g_shift[o+0]), 0.f);
    r.y = fmaxf(fmaf(a1, (a1 >= 0.f) ? mx.y : mn.y, g_shift[o+1]), 0.f);
    r.z = fmaxf(fmaf(a2, (a2 >= 0.f) ? mx.z : mn.z, g_shift[o+2]), 0.f);
    r.w = fmaxf(fmaf(a3, (a3 >= 0.f) ? mx.w : mn.w, g_shift[o+3]), 0.f);
    ((float4*)out)[t] = r;
}

extern "C" void kernel_launch(void* const* d_in, const int* in_sizes, int n_in,
                              void* d_out, int out_size) {
    const float* x     = (const float*)d_in[0];
    const float* W     = (const float*)d_in[1];
    // d_in[2] (conv bias b) cancels exactly under BatchNorm: unused.
    const float* gamma = (const float*)d_in[3];
    const float* beta  = (const float*)d_in[4];
    float* out = (float*)d_out;

    cudaFuncSetAttribute(k_knn, cudaFuncAttributeMaxDynamicSharedMemorySize, SM_TOTAL);

    k_split<<<NPTS*FF/512, 256>>>(x);
    k_uv   <<<NPTS/64, 256>>>(x, W);
    k_knn  <<<dim3(NN/ITILE, BB), 128, SM_TOTAL>>>();
    k_fuse <<<NPTS/64, 256>>>(gamma, beta);
    k_final<<<NPTS*OO/1024, 256>>>(out);
}